// round 1
// baseline (speedup 1.0000x reference)
#include <cuda_runtime.h>
#include <cuda_bf16.h>
#include <math.h>

// Problem constants
#define S_LEN 4096
#define D_MODEL 1024
#define H_HEADS 16
#define D_HEAD 64
#define WIN 512
#define PADS 256

// Scratch (static device globals — no allocation)
__device__ float g_qkv[S_LEN * 3 * D_MODEL];  // [s][which*1024 + h*64 + dd]
__device__ float g_o[S_LEN * D_MODEL];        // [s][h*64 + dd]

// ---------------------------------------------------------------------------
// SGEMM: C[M,N] = A[M,K] @ B[N,K]^T + bias[N]   (both row-major, dot over K)
// BM=BN=128, BK=16, 256 threads, 8x8 microtile.
// ---------------------------------------------------------------------------
__global__ __launch_bounds__(256) void sgemm_nt_bias(
    const float* __restrict__ A, const float* __restrict__ B,
    const float* __restrict__ bias, float* __restrict__ C,
    int M, int N, int K)
{
    __shared__ float As[16][128];
    __shared__ float Bs[16][128];

    const int tid = threadIdx.x;
    const int tx = tid & 15;
    const int ty = tid >> 4;
    const int m0 = blockIdx.y * 128;
    const int n0 = blockIdx.x * 128;

    const int lr = tid >> 1;        // 0..127 (row within tile)
    const int lc = (tid & 1) * 8;   // 0 or 8 (col within BK)

    const float* Ap = A + (size_t)(m0 + lr) * K + lc;
    const float* Bp = B + (size_t)(n0 + lr) * K + lc;

    float acc[8][8];
#pragma unroll
    for (int i = 0; i < 8; i++)
#pragma unroll
        for (int j = 0; j < 8; j++) acc[i][j] = 0.0f;

    for (int k0 = 0; k0 < K; k0 += 16) {
        float4 a0 = *(const float4*)(Ap + k0);
        float4 a1 = *(const float4*)(Ap + k0 + 4);
        float4 b0 = *(const float4*)(Bp + k0);
        float4 b1 = *(const float4*)(Bp + k0 + 4);

        __syncthreads();  // previous compute done before overwriting smem
        As[lc + 0][lr] = a0.x; As[lc + 1][lr] = a0.y;
        As[lc + 2][lr] = a0.z; As[lc + 3][lr] = a0.w;
        As[lc + 4][lr] = a1.x; As[lc + 5][lr] = a1.y;
        As[lc + 6][lr] = a1.z; As[lc + 7][lr] = a1.w;
        Bs[lc + 0][lr] = b0.x; Bs[lc + 1][lr] = b0.y;
        Bs[lc + 2][lr] = b0.z; Bs[lc + 3][lr] = b0.w;
        Bs[lc + 4][lr] = b1.x; Bs[lc + 5][lr] = b1.y;
        Bs[lc + 6][lr] = b1.z; Bs[lc + 7][lr] = b1.w;
        __syncthreads();

#pragma unroll
        for (int kk = 0; kk < 16; kk++) {
            float af[8], bf[8];
            *(float4*)&af[0] = *(const float4*)&As[kk][ty * 8];
            *(float4*)&af[4] = *(const float4*)&As[kk][ty * 8 + 4];
            *(float4*)&bf[0] = *(const float4*)&Bs[kk][tx * 8];
            *(float4*)&bf[4] = *(const float4*)&Bs[kk][tx * 8 + 4];
#pragma unroll
            for (int i = 0; i < 8; i++)
#pragma unroll
                for (int j = 0; j < 8; j++)
                    acc[i][j] += af[i] * bf[j];
        }
    }

    float bs[8];
#pragma unroll
    for (int j = 0; j < 8; j++) bs[j] = bias[n0 + tx * 8 + j];

#pragma unroll
    for (int i = 0; i < 8; i++) {
        const int row = m0 + ty * 8 + i;
        float* Cp = C + (size_t)row * N + n0 + tx * 8;
        float4 r0, r1;
        r0.x = acc[i][0] + bs[0]; r0.y = acc[i][1] + bs[1];
        r0.z = acc[i][2] + bs[2]; r0.w = acc[i][3] + bs[3];
        r1.x = acc[i][4] + bs[4]; r1.y = acc[i][5] + bs[5];
        r1.z = acc[i][6] + bs[6]; r1.w = acc[i][7] + bs[7];
        *(float4*)(Cp + 0) = r0;
        *(float4*)(Cp + 4) = r1;
    }
}

// ---------------------------------------------------------------------------
// Sliding-window attention, flash style.
// Block = (head h, 64-query chunk). 9 key tiles of 64 cover [q0-256, q0+318].
// Out-of-range keys/values are loaded as ZERO and kept inside the band
// (reference includes padded zeros in the softmax denominator).
// Band: valid iff 0 <= (jglobal - iglobal + 256) <= 511,
// i.e. local (t*64 + jk) - iq in [0, 511].
// SMEM: QT[64][64] (dd-major), KT[64][64] (dd-major), Vs[64][68], Ps[64][68].
// ---------------------------------------------------------------------------
#define ATTN_SMEM_FLOATS (64*64 + 64*64 + 64*68 + 64*68)
#define ATTN_SMEM_BYTES (ATTN_SMEM_FLOATS * 4)

__global__ __launch_bounds__(256) void attn_kernel(
    const float* __restrict__ qkv, float* __restrict__ o_out)
{
    extern __shared__ float sm[];
    float* QT = sm;                 // QT[dd*64 + i]
    float* KT = QT + 64 * 64;       // KT[dd*64 + j]
    float* Vs = KT + 64 * 64;       // Vs[j*68 + dd]
    float* Ps = Vs + 64 * 68;       // Ps[i*68 + j]

    const int h = blockIdx.y;
    const int q0 = blockIdx.x * 64;
    const int tid = threadIdx.x;
    const int tx = tid & 15;   // key / dim tile coord
    const int ty = tid >> 4;   // query tile coord
    const float scale = 0.125f;  // 1/sqrt(64)

    // Load Q transposed: QT[dd][i]
    for (int idx = tid; idx < 1024; idx += 256) {
        const int row = idx >> 4;           // query row 0..63
        const int seg = (idx & 15) * 4;     // dim 0..60
        float4 v = *(const float4*)(qkv + (size_t)(q0 + row) * 3072 + h * 64 + seg);
        QT[(seg + 0) * 64 + row] = v.x;
        QT[(seg + 1) * 64 + row] = v.y;
        QT[(seg + 2) * 64 + row] = v.z;
        QT[(seg + 3) * 64 + row] = v.w;
    }

    float m_run[4], l_run[4], o[4][4];
#pragma unroll
    for (int q = 0; q < 4; q++) {
        m_run[q] = -INFINITY;
        l_run[q] = 0.0f;
#pragma unroll
        for (int k = 0; k < 4; k++) o[q][k] = 0.0f;
    }

    for (int t = 0; t < 9; t++) {
        const int j0 = q0 - 256 + t * 64;

        __syncthreads();  // previous PV done reading KT/Vs/Ps

        // Load K (transposed) and V tiles, zero-filling out-of-range rows
        for (int idx = tid; idx < 1024; idx += 256) {
            const int row = idx >> 4;
            const int seg = (idx & 15) * 4;
            const int j = j0 + row;
            float4 kv = make_float4(0.f, 0.f, 0.f, 0.f);
            float4 vv = make_float4(0.f, 0.f, 0.f, 0.f);
            if (j >= 0 && j < S_LEN) {
                const float* base = qkv + (size_t)j * 3072 + h * 64 + seg;
                kv = *(const float4*)(base + 1024);
                vv = *(const float4*)(base + 2048);
            }
            KT[(seg + 0) * 64 + row] = kv.x;
            KT[(seg + 1) * 64 + row] = kv.y;
            KT[(seg + 2) * 64 + row] = kv.z;
            KT[(seg + 3) * 64 + row] = kv.w;
            *(float4*)&Vs[row * 68 + seg] = vv;
        }
        __syncthreads();

        // S = Q K^T for this tile (4x4 microtile)
        float s[4][4];
#pragma unroll
        for (int q = 0; q < 4; q++)
#pragma unroll
            for (int k = 0; k < 4; k++) s[q][k] = 0.0f;

#pragma unroll 16
        for (int dd = 0; dd < 64; dd++) {
            float4 qa = *(const float4*)&QT[dd * 64 + ty * 4];
            float4 kb = *(const float4*)&KT[dd * 64 + tx * 4];
            const float qf[4] = {qa.x, qa.y, qa.z, qa.w};
            const float kf[4] = {kb.x, kb.y, kb.z, kb.w};
#pragma unroll
            for (int q = 0; q < 4; q++)
#pragma unroll
                for (int k = 0; k < 4; k++)
                    s[q][k] += qf[q] * kf[k];
        }

        // Band mask + online softmax update
#pragma unroll
        for (int q = 0; q < 4; q++) {
            const int iq = ty * 4 + q;
            float mx = -INFINITY;
#pragma unroll
            for (int k = 0; k < 4; k++) {
                const int jj = t * 64 + tx * 4 + k;  // local key coord
                const int rel = jj - iq;             // band iff 0 <= rel <= 511
                if (rel >= 0 && rel <= 511) {
                    s[q][k] *= scale;
                } else {
                    s[q][k] = -INFINITY;
                }
                mx = fmaxf(mx, s[q][k]);
            }
            // reduce max over the 16-lane key group
#pragma unroll
            for (int msk = 1; msk <= 8; msk <<= 1)
                mx = fmaxf(mx, __shfl_xor_sync(0xFFFFFFFFu, mx, msk));

            const float m_new = fmaxf(m_run[q], mx);
            const float cc = __expf(m_run[q] - m_new);  // m_new finite after t=0
            m_run[q] = m_new;

            float rs = 0.0f;
#pragma unroll
            for (int k = 0; k < 4; k++) {
                const float p = __expf(s[q][k] - m_new);  // exp(-inf)=0 for masked
                s[q][k] = p;
                rs += p;
            }
#pragma unroll
            for (int msk = 1; msk <= 8; msk <<= 1)
                rs += __shfl_xor_sync(0xFFFFFFFFu, rs, msk);

            l_run[q] = l_run[q] * cc + rs;
#pragma unroll
            for (int k = 0; k < 4; k++) o[q][k] *= cc;
        }

        // Write P tile (row-major, padded stride 68), vectorized
#pragma unroll
        for (int q = 0; q < 4; q++) {
            float4 pv = make_float4(s[q][0], s[q][1], s[q][2], s[q][3]);
            *(float4*)&Ps[(ty * 4 + q) * 68 + tx * 4] = pv;
        }
        __syncthreads();

        // O += P V  (k-loop over the 64 keys of this tile)
#pragma unroll 16
        for (int j = 0; j < 64; j++) {
            float4 vv = *(const float4*)&Vs[j * 68 + tx * 4];
            const float vf[4] = {vv.x, vv.y, vv.z, vv.w};
            float pa[4];
#pragma unroll
            for (int q = 0; q < 4; q++) pa[q] = Ps[(ty * 4 + q) * 68 + j];
#pragma unroll
            for (int q = 0; q < 4; q++)
#pragma unroll
                for (int k = 0; k < 4; k++)
                    o[q][k] += pa[q] * vf[k];
        }
    }

    // Normalize and store: o_out[s][h*64 + dd]
#pragma unroll
    for (int q = 0; q < 4; q++) {
        const float inv_l = 1.0f / l_run[q];
        float4 ov;
        ov.x = o[q][0] * inv_l;
        ov.y = o[q][1] * inv_l;
        ov.z = o[q][2] * inv_l;
        ov.w = o[q][3] * inv_l;
        *(float4*)(o_out + (size_t)(q0 + ty * 4 + q) * D_MODEL + h * 64 + tx * 4) = ov;
    }
}

// ---------------------------------------------------------------------------
extern "C" void kernel_launch(void* const* d_in, const int* in_sizes, int n_in,
                              void* d_out, int out_size)
{
    const float* x    = (const float*)d_in[0];
    const float* Wqkv = (const float*)d_in[1];
    const float* bqkv = (const float*)d_in[2];
    const float* Wout = (const float*)d_in[3];
    const float* bout = (const float*)d_in[4];
    float* out = (float*)d_out;
    (void)in_sizes; (void)n_in; (void)out_size;

    float* qkv_p = nullptr;
    float* o_p = nullptr;
    cudaGetSymbolAddress((void**)&qkv_p, g_qkv);
    cudaGetSymbolAddress((void**)&o_p, g_o);

    cudaFuncSetAttribute(attn_kernel,
                         cudaFuncAttributeMaxDynamicSharedMemorySize,
                         ATTN_SMEM_BYTES);

    // 1) QKV projection: [4096,3072] = x[4096,1024] @ Wqkv[3072,1024]^T + bqkv
    {
        dim3 grid(3072 / 128, S_LEN / 128);
        sgemm_nt_bias<<<grid, 256>>>(x, Wqkv, bqkv, qkv_p, S_LEN, 3 * D_MODEL, D_MODEL);
    }

    // 2) Sliding-window attention
    {
        dim3 grid(S_LEN / 64, H_HEADS);
        attn_kernel<<<grid, 256, ATTN_SMEM_BYTES>>>(qkv_p, o_p);
    }

    // 3) Output projection: [4096,1024] = o[4096,1024] @ Wout[1024,1024]^T + bout
    {
        dim3 grid(D_MODEL / 128, S_LEN / 128);
        sgemm_nt_bias<<<grid, 256>>>(o_p, Wout, bout, out, S_LEN, D_MODEL, D_MODEL);
    }
}

// round 3
// speedup vs baseline: 1.8104x; 1.8104x over previous
#include <cuda_runtime.h>
#include <cuda_bf16.h>
#include <math.h>
#include <cstdint>

// Problem constants
#define S_LEN 4096
#define D_MODEL 1024
#define H_HEADS 16
#define D_HEAD 64
#define WIN 512

// ---------------------------------------------------------------------------
// Scratch (static device globals — no allocation)
// ---------------------------------------------------------------------------
__device__ float g_qkv[S_LEN * 3 * D_MODEL];  // [s][which*1024 + h*64 + dd]
__device__ float g_o[S_LEN * D_MODEL];        // [s][h*64 + dd]

__device__ __nv_bfloat16 g_xh[S_LEN * D_MODEL];
__device__ __nv_bfloat16 g_xl[S_LEN * D_MODEL];
__device__ __nv_bfloat16 g_wqh[3 * D_MODEL * D_MODEL];
__device__ __nv_bfloat16 g_wql[3 * D_MODEL * D_MODEL];
__device__ __nv_bfloat16 g_woh[D_MODEL * D_MODEL];
__device__ __nv_bfloat16 g_wol[D_MODEL * D_MODEL];
__device__ __nv_bfloat16 g_oh[S_LEN * D_MODEL];
__device__ __nv_bfloat16 g_ol[S_LEN * D_MODEL];

// ---------------------------------------------------------------------------
// Helpers
// ---------------------------------------------------------------------------
__device__ __forceinline__ uint32_t smem_u32(const void* p) {
    uint32_t a;
    asm("{ .reg .u64 t; cvta.to.shared.u64 t, %1; cvt.u32.u64 %0, t; }"
        : "=r"(a) : "l"(p));
    return a;
}

#define SWZ128(off) ((off) ^ (((off) >> 3) & 0x70))

#define CP_ASYNC16(dst, src) \
    asm volatile("cp.async.cg.shared.global [%0], [%1], 16;" \
        :: "r"(dst), "l"(src))
#define CP_COMMIT()  asm volatile("cp.async.commit_group;" ::: "memory")
#define CP_WAIT(n)   asm volatile("cp.async.wait_group %0;" :: "n"(n) : "memory")

#define LDSM4(r, addr) \
    asm volatile("ldmatrix.sync.aligned.m8n8.x4.shared.b16 {%0,%1,%2,%3}, [%4];" \
        : "=r"((r)[0]), "=r"((r)[1]), "=r"((r)[2]), "=r"((r)[3]) : "r"(addr))

#define MMA16816(d, a, b0, b1) \
    asm volatile("mma.sync.aligned.m16n8k16.row.col.f32.bf16.bf16.f32 " \
        "{%0,%1,%2,%3}, {%4,%5,%6,%7}, {%8,%9}, {%0,%1,%2,%3};" \
        : "+f"((d)[0]), "+f"((d)[1]), "+f"((d)[2]), "+f"((d)[3]) \
        : "r"((a)[0]), "r"((a)[1]), "r"((a)[2]), "r"((a)[3]), \
          "r"(b0), "r"(b1))

// ---------------------------------------------------------------------------
// Split fp32 -> (bf16 hi, bf16 lo), vectorized x4
// ---------------------------------------------------------------------------
__global__ void split_bf16(const float* __restrict__ in,
                           __nv_bfloat16* __restrict__ hi,
                           __nv_bfloat16* __restrict__ lo, int n4)
{
    int i = blockIdx.x * blockDim.x + threadIdx.x;
    if (i >= n4) return;
    float4 v = ((const float4*)in)[i];
    __nv_bfloat16 h0 = __float2bfloat16(v.x);
    __nv_bfloat16 h1 = __float2bfloat16(v.y);
    __nv_bfloat16 h2 = __float2bfloat16(v.z);
    __nv_bfloat16 h3 = __float2bfloat16(v.w);
    __nv_bfloat162 hh0; hh0.x = h0; hh0.y = h1;
    __nv_bfloat162 hh1; hh1.x = h2; hh1.y = h3;
    __nv_bfloat162 ll0, ll1;
    ll0.x = __float2bfloat16(v.x - __bfloat162float(h0));
    ll0.y = __float2bfloat16(v.y - __bfloat162float(h1));
    ll1.x = __float2bfloat16(v.z - __bfloat162float(h2));
    ll1.y = __float2bfloat16(v.w - __bfloat162float(h3));
    ((__nv_bfloat162*)hi)[i * 2 + 0] = hh0;
    ((__nv_bfloat162*)hi)[i * 2 + 1] = hh1;
    ((__nv_bfloat162*)lo)[i * 2 + 0] = ll0;
    ((__nv_bfloat162*)lo)[i * 2 + 1] = ll1;
}

// ---------------------------------------------------------------------------
// bf16x3 GEMM via mma.sync: C[M,N] = Ah@Bh^T + Ah@Bl^T + Al@Bh^T + bias
// A[M,K], B[N,K] row-major bf16; C fp32 row-major.
// CTA tile 128x128x64, 8 warps (2x4), warp tile 64x32.
// SMEM: 128B rows + SW128 swizzle; cp.async 2-stage pipeline.
// ---------------------------------------------------------------------------
#define GBM 128
#define GBN 128
#define GBK 64
#define TILE_B (GBM * GBK * 2)      // 16384 bytes per matrix tile
#define STAGE_B (4 * TILE_B)        // Ah, Al, Bh, Bl
#define GEMM_SMEM (2 * STAGE_B)     // 131072

__device__ __forceinline__ void cp_tile(
    uint32_t sbase, const __nv_bfloat16* __restrict__ g,
    int r0, int k0, int ldk, int tid)
{
    // 128 rows x 8 chunks of 16B
#pragma unroll
    for (int it = 0; it < 4; it++) {
        int idx = tid + it * 256;
        int row = idx >> 3;
        int ch = idx & 7;
        uint32_t so = sbase + SWZ128((uint32_t)(row * 128 + ch * 16));
        const void* gp = (const void*)(g + (size_t)(r0 + row) * ldk + k0 + ch * 8);
        CP_ASYNC16(so, gp);
    }
}

__global__ __launch_bounds__(256, 1) void gemm_bf16x3(
    const __nv_bfloat16* __restrict__ Ah, const __nv_bfloat16* __restrict__ Al,
    const __nv_bfloat16* __restrict__ Bh, const __nv_bfloat16* __restrict__ Bl,
    const float* __restrict__ bias, float* __restrict__ C,
    int M, int N, int K)
{
    extern __shared__ char smem[];
    const uint32_t sb = smem_u32(smem);
    const int tid = threadIdx.x;
    const int wid = tid >> 5;
    const int lane = tid & 31;
    const int wm = wid >> 2;          // 0..1
    const int wn = wid & 3;           // 0..3
    const int m0 = blockIdx.y * GBM;
    const int n0 = blockIdx.x * GBN;

    float acc[4][4][4];
#pragma unroll
    for (int mf = 0; mf < 4; mf++)
#pragma unroll
        for (int nf = 0; nf < 4; nf++)
#pragma unroll
            for (int r = 0; r < 4; r++) acc[mf][nf][r] = 0.0f;

    // Per-lane base byte offsets inside a tile (before swizzle)
    const uint32_t arow = (uint32_t)(wm * 64 + (lane & 15));
    const uint32_t brow = (uint32_t)(wn * 32 + (lane & 15));
    const uint32_t khalf = (uint32_t)((lane >> 4) << 4);   // 0 or 16 bytes

    const int nk = K / GBK;

    // Prologue: load stage 0
    {
        cp_tile(sb + 0 * TILE_B, Ah, m0, 0, K, tid);
        cp_tile(sb + 1 * TILE_B, Al, m0, 0, K, tid);
        cp_tile(sb + 2 * TILE_B, Bh, n0, 0, K, tid);
        cp_tile(sb + 3 * TILE_B, Bl, n0, 0, K, tid);
        CP_COMMIT();
    }

    for (int c = 0; c < nk; c++) {
        const uint32_t st = (uint32_t)(c & 1) * STAGE_B;
        if (c + 1 < nk) {
            const uint32_t st2 = (uint32_t)((c + 1) & 1) * STAGE_B;
            const int k0 = (c + 1) * GBK;
            cp_tile(sb + st2 + 0 * TILE_B, Ah, m0, k0, K, tid);
            cp_tile(sb + st2 + 1 * TILE_B, Al, m0, k0, K, tid);
            cp_tile(sb + st2 + 2 * TILE_B, Bh, n0, k0, K, tid);
            cp_tile(sb + st2 + 3 * TILE_B, Bl, n0, k0, K, tid);
            CP_COMMIT();
            CP_WAIT(1);
        } else {
            CP_WAIT(0);
        }
        __syncthreads();

        const uint32_t aH = sb + st + 0 * TILE_B;
        const uint32_t aL = sb + st + 1 * TILE_B;
        const uint32_t bH = sb + st + 2 * TILE_B;
        const uint32_t bL = sb + st + 3 * TILE_B;

#pragma unroll
        for (int ks = 0; ks < 4; ks++) {
            const uint32_t kb = (uint32_t)(ks * 32) + khalf;
            uint32_t ah[4][4], al[4][4], bh[2][4], bl[2][4];
#pragma unroll
            for (int mf = 0; mf < 4; mf++) {
                uint32_t off = SWZ128((arow + mf * 16) * 128 + kb);
                LDSM4(ah[mf], aH + off);
                LDSM4(al[mf], aL + off);
            }
#pragma unroll
            for (int nf2 = 0; nf2 < 2; nf2++) {
                uint32_t off = SWZ128((brow + nf2 * 16) * 128 + kb);
                LDSM4(bh[nf2], bH + off);
                LDSM4(bl[nf2], bL + off);
            }
#pragma unroll
            for (int mf = 0; mf < 4; mf++) {
#pragma unroll
                for (int nf2 = 0; nf2 < 2; nf2++) {
                    MMA16816(acc[mf][nf2 * 2 + 0], ah[mf], bh[nf2][0], bh[nf2][2]);
                    MMA16816(acc[mf][nf2 * 2 + 1], ah[mf], bh[nf2][1], bh[nf2][3]);
                    MMA16816(acc[mf][nf2 * 2 + 0], ah[mf], bl[nf2][0], bl[nf2][2]);
                    MMA16816(acc[mf][nf2 * 2 + 1], ah[mf], bl[nf2][1], bl[nf2][3]);
                    MMA16816(acc[mf][nf2 * 2 + 0], al[mf], bh[nf2][0], bh[nf2][2]);
                    MMA16816(acc[mf][nf2 * 2 + 1], al[mf], bh[nf2][1], bh[nf2][3]);
                }
            }
        }
        __syncthreads();
    }

    // Epilogue: add bias, store fp32
#pragma unroll
    for (int mf = 0; mf < 4; mf++) {
        const int mrow = m0 + wm * 64 + mf * 16 + (lane >> 2);
#pragma unroll
        for (int nf = 0; nf < 4; nf++) {
            const int ncol = n0 + wn * 32 + nf * 8 + (lane & 3) * 2;
            const float b0 = bias[ncol];
            const float b1 = bias[ncol + 1];
            float2 v0, v1;
            v0.x = acc[mf][nf][0] + b0; v0.y = acc[mf][nf][1] + b1;
            v1.x = acc[mf][nf][2] + b0; v1.y = acc[mf][nf][3] + b1;
            *(float2*)(C + (size_t)mrow * N + ncol) = v0;
            *(float2*)(C + (size_t)(mrow + 8) * N + ncol) = v1;
        }
    }
}

// ---------------------------------------------------------------------------
// Sliding-window attention (fp32 flash-style, proven in round 1)
// ---------------------------------------------------------------------------
#define ATTN_SMEM_FLOATS (64*64 + 64*64 + 64*68 + 64*68)
#define ATTN_SMEM_BYTES (ATTN_SMEM_FLOATS * 4)

__global__ __launch_bounds__(256) void attn_kernel(
    const float* __restrict__ qkv, float* __restrict__ o_out)
{
    extern __shared__ float sm[];
    float* QT = sm;
    float* KT = QT + 64 * 64;
    float* Vs = KT + 64 * 64;
    float* Ps = Vs + 64 * 68;

    const int h = blockIdx.y;
    const int q0 = blockIdx.x * 64;
    const int tid = threadIdx.x;
    const int tx = tid & 15;
    const int ty = tid >> 4;
    const float scale = 0.125f;

    for (int idx = tid; idx < 1024; idx += 256) {
        const int row = idx >> 4;
        const int seg = (idx & 15) * 4;
        float4 v = *(const float4*)(qkv + (size_t)(q0 + row) * 3072 + h * 64 + seg);
        QT[(seg + 0) * 64 + row] = v.x;
        QT[(seg + 1) * 64 + row] = v.y;
        QT[(seg + 2) * 64 + row] = v.z;
        QT[(seg + 3) * 64 + row] = v.w;
    }

    float m_run[4], l_run[4], o[4][4];
#pragma unroll
    for (int q = 0; q < 4; q++) {
        m_run[q] = -INFINITY;
        l_run[q] = 0.0f;
#pragma unroll
        for (int k = 0; k < 4; k++) o[q][k] = 0.0f;
    }

    for (int t = 0; t < 9; t++) {
        const int j0 = q0 - 256 + t * 64;
        __syncthreads();
        for (int idx = tid; idx < 1024; idx += 256) {
            const int row = idx >> 4;
            const int seg = (idx & 15) * 4;
            const int j = j0 + row;
            float4 kv = make_float4(0.f, 0.f, 0.f, 0.f);
            float4 vv = make_float4(0.f, 0.f, 0.f, 0.f);
            if (j >= 0 && j < S_LEN) {
                const float* base = qkv + (size_t)j * 3072 + h * 64 + seg;
                kv = *(const float4*)(base + 1024);
                vv = *(const float4*)(base + 2048);
            }
            KT[(seg + 0) * 64 + row] = kv.x;
            KT[(seg + 1) * 64 + row] = kv.y;
            KT[(seg + 2) * 64 + row] = kv.z;
            KT[(seg + 3) * 64 + row] = kv.w;
            *(float4*)&Vs[row * 68 + seg] = vv;
        }
        __syncthreads();

        float s[4][4];
#pragma unroll
        for (int q = 0; q < 4; q++)
#pragma unroll
            for (int k = 0; k < 4; k++) s[q][k] = 0.0f;

#pragma unroll 16
        for (int dd = 0; dd < 64; dd++) {
            float4 qa = *(const float4*)&QT[dd * 64 + ty * 4];
            float4 kb = *(const float4*)&KT[dd * 64 + tx * 4];
            const float qf[4] = {qa.x, qa.y, qa.z, qa.w};
            const float kf[4] = {kb.x, kb.y, kb.z, kb.w};
#pragma unroll
            for (int q = 0; q < 4; q++)
#pragma unroll
                for (int k = 0; k < 4; k++)
                    s[q][k] += qf[q] * kf[k];
        }

#pragma unroll
        for (int q = 0; q < 4; q++) {
            const int iq = ty * 4 + q;
            float mx = -INFINITY;
#pragma unroll
            for (int k = 0; k < 4; k++) {
                const int jj = t * 64 + tx * 4 + k;
                const int rel = jj - iq;
                if (rel >= 0 && rel <= 511) {
                    s[q][k] *= scale;
                } else {
                    s[q][k] = -INFINITY;
                }
                mx = fmaxf(mx, s[q][k]);
            }
#pragma unroll
            for (int msk = 1; msk <= 8; msk <<= 1)
                mx = fmaxf(mx, __shfl_xor_sync(0xFFFFFFFFu, mx, msk));

            const float m_new = fmaxf(m_run[q], mx);
            const float cc = __expf(m_run[q] - m_new);
            m_run[q] = m_new;

            float rs = 0.0f;
#pragma unroll
            for (int k = 0; k < 4; k++) {
                const float p = __expf(s[q][k] - m_new);
                s[q][k] = p;
                rs += p;
            }
#pragma unroll
            for (int msk = 1; msk <= 8; msk <<= 1)
                rs += __shfl_xor_sync(0xFFFFFFFFu, rs, msk);

            l_run[q] = l_run[q] * cc + rs;
#pragma unroll
            for (int k = 0; k < 4; k++) o[q][k] *= cc;
        }

#pragma unroll
        for (int q = 0; q < 4; q++) {
            float4 pv = make_float4(s[q][0], s[q][1], s[q][2], s[q][3]);
            *(float4*)&Ps[(ty * 4 + q) * 68 + tx * 4] = pv;
        }
        __syncthreads();

#pragma unroll 16
        for (int j = 0; j < 64; j++) {
            float4 vv = *(const float4*)&Vs[j * 68 + tx * 4];
            const float vf[4] = {vv.x, vv.y, vv.z, vv.w};
            float pa[4];
#pragma unroll
            for (int q = 0; q < 4; q++) pa[q] = Ps[(ty * 4 + q) * 68 + j];
#pragma unroll
            for (int q = 0; q < 4; q++)
#pragma unroll
                for (int k = 0; k < 4; k++)
                    o[q][k] += pa[q] * vf[k];
        }
    }

#pragma unroll
    for (int q = 0; q < 4; q++) {
        const float inv_l = 1.0f / l_run[q];
        float4 ov;
        ov.x = o[q][0] * inv_l;
        ov.y = o[q][1] * inv_l;
        ov.z = o[q][2] * inv_l;
        ov.w = o[q][3] * inv_l;
        *(float4*)(o_out + (size_t)(q0 + ty * 4 + q) * D_MODEL + h * 64 + tx * 4) = ov;
    }
}

// ---------------------------------------------------------------------------
extern "C" void kernel_launch(void* const* d_in, const int* in_sizes, int n_in,
                              void* d_out, int out_size)
{
    const float* x    = (const float*)d_in[0];
    const float* Wqkv = (const float*)d_in[1];
    const float* bqkv = (const float*)d_in[2];
    const float* Wout = (const float*)d_in[3];
    const float* bout = (const float*)d_in[4];
    float* out = (float*)d_out;
    (void)in_sizes; (void)n_in; (void)out_size;

    float *qkv_p, *o_p;
    __nv_bfloat16 *xh, *xl, *wqh, *wql, *woh, *wol, *oh, *ol;
    cudaGetSymbolAddress((void**)&qkv_p, g_qkv);
    cudaGetSymbolAddress((void**)&o_p, g_o);
    cudaGetSymbolAddress((void**)&xh, g_xh);
    cudaGetSymbolAddress((void**)&xl, g_xl);
    cudaGetSymbolAddress((void**)&wqh, g_wqh);
    cudaGetSymbolAddress((void**)&wql, g_wql);
    cudaGetSymbolAddress((void**)&woh, g_woh);
    cudaGetSymbolAddress((void**)&wol, g_wol);
    cudaGetSymbolAddress((void**)&oh, g_oh);
    cudaGetSymbolAddress((void**)&ol, g_ol);

    cudaFuncSetAttribute(gemm_bf16x3,
                         cudaFuncAttributeMaxDynamicSharedMemorySize, GEMM_SMEM);
    cudaFuncSetAttribute(attn_kernel,
                         cudaFuncAttributeMaxDynamicSharedMemorySize, ATTN_SMEM_BYTES);

    // Splits
    {
        int n4 = (S_LEN * D_MODEL) / 4;
        split_bf16<<<(n4 + 255) / 256, 256>>>(x, xh, xl, n4);
    }
    {
        int n4 = (3 * D_MODEL * D_MODEL) / 4;
        split_bf16<<<(n4 + 255) / 256, 256>>>(Wqkv, wqh, wql, n4);
    }
    {
        int n4 = (D_MODEL * D_MODEL) / 4;
        split_bf16<<<(n4 + 255) / 256, 256>>>(Wout, woh, wol, n4);
    }

    // 1) QKV projection: [4096,3072]
    {
        dim3 grid(3 * D_MODEL / GBN, S_LEN / GBM);
        gemm_bf16x3<<<grid, 256, GEMM_SMEM>>>(xh, xl, wqh, wql, bqkv, qkv_p,
                                              S_LEN, 3 * D_MODEL, D_MODEL);
    }

    // 2) Sliding-window attention
    {
        dim3 grid(S_LEN / 64, H_HEADS);
        attn_kernel<<<grid, 256, ATTN_SMEM_BYTES>>>(qkv_p, o_p);
    }

    // 3) Split attention output, then output projection
    {
        int n4 = (S_LEN * D_MODEL) / 4;
        split_bf16<<<(n4 + 255) / 256, 256>>>(o_p, oh, ol, n4);
    }
    {
        dim3 grid(D_MODEL / GBN, S_LEN / GBM);
        gemm_bf16x3<<<grid, 256, GEMM_SMEM>>>(oh, ol, woh, wol, bout, out,
                                              S_LEN, D_MODEL, D_MODEL);
    }
}

// round 4
// speedup vs baseline: 2.6630x; 1.4710x over previous
#include <cuda_runtime.h>
#include <cuda_bf16.h>
#include <math.h>
#include <cstdint>

// Problem constants
#define S_LEN 4096
#define D_MODEL 1024
#define H_HEADS 16
#define D_HEAD 64
#define WIN 512

// ---------------------------------------------------------------------------
// Scratch (static device globals — no allocation)
// ---------------------------------------------------------------------------
__device__ float g_qkv[S_LEN * 3 * D_MODEL];  // [s][which*1024 + h*64 + dd]

__device__ __nv_bfloat16 g_xh[S_LEN * D_MODEL];
__device__ __nv_bfloat16 g_xl[S_LEN * D_MODEL];
__device__ __nv_bfloat16 g_wqh[3 * D_MODEL * D_MODEL];
__device__ __nv_bfloat16 g_wql[3 * D_MODEL * D_MODEL];
__device__ __nv_bfloat16 g_woh[D_MODEL * D_MODEL];
__device__ __nv_bfloat16 g_wol[D_MODEL * D_MODEL];
__device__ __nv_bfloat16 g_oh[S_LEN * D_MODEL];
__device__ __nv_bfloat16 g_ol[S_LEN * D_MODEL];

// ---------------------------------------------------------------------------
// Helpers
// ---------------------------------------------------------------------------
__device__ __forceinline__ uint32_t smem_u32(const void* p) {
    uint32_t a;
    asm("{ .reg .u64 t; cvta.to.shared.u64 t, %1; cvt.u32.u64 %0, t; }"
        : "=r"(a) : "l"(p));
    return a;
}

#define SWZ128(off) ((off) ^ (((off) >> 3) & 0x70))

#define CP_ASYNC16(dst, src) \
    asm volatile("cp.async.cg.shared.global [%0], [%1], 16;" \
        :: "r"(dst), "l"(src))
#define CP_COMMIT()  asm volatile("cp.async.commit_group;" ::: "memory")
#define CP_WAIT(n)   asm volatile("cp.async.wait_group %0;" :: "n"(n) : "memory")

#define LDSM4(r, addr) \
    asm volatile("ldmatrix.sync.aligned.m8n8.x4.shared.b16 {%0,%1,%2,%3}, [%4];" \
        : "=r"((r)[0]), "=r"((r)[1]), "=r"((r)[2]), "=r"((r)[3]) : "r"(addr))

#define LDSM4T(r, addr) \
    asm volatile("ldmatrix.sync.aligned.m8n8.x4.trans.shared.b16 {%0,%1,%2,%3}, [%4];" \
        : "=r"((r)[0]), "=r"((r)[1]), "=r"((r)[2]), "=r"((r)[3]) : "r"(addr))

#define MMA16816(d, a, b0, b1) \
    asm volatile("mma.sync.aligned.m16n8k16.row.col.f32.bf16.bf16.f32 " \
        "{%0,%1,%2,%3}, {%4,%5,%6,%7}, {%8,%9}, {%0,%1,%2,%3};" \
        : "+f"((d)[0]), "+f"((d)[1]), "+f"((d)[2]), "+f"((d)[3]) \
        : "r"((a)[0]), "r"((a)[1]), "r"((a)[2]), "r"((a)[3]), \
          "r"(b0), "r"(b1))

// Split two floats into packed bf16x2 hi and residual-lo (lo half = first arg)
__device__ __forceinline__ void split2(float a, float b,
                                       uint32_t& hi, uint32_t& lo) {
    __nv_bfloat16 ha = __float2bfloat16(a);
    __nv_bfloat16 hb = __float2bfloat16(b);
    __nv_bfloat162 H; H.x = ha; H.y = hb;
    __nv_bfloat162 L;
    L.x = __float2bfloat16(a - __bfloat162float(ha));
    L.y = __float2bfloat16(b - __bfloat162float(hb));
    hi = *(uint32_t*)&H;
    lo = *(uint32_t*)&L;
}

// ---------------------------------------------------------------------------
// Split fp32 -> (bf16 hi, bf16 lo), vectorized x4
// ---------------------------------------------------------------------------
__global__ void split_bf16(const float* __restrict__ in,
                           __nv_bfloat16* __restrict__ hi,
                           __nv_bfloat16* __restrict__ lo, int n4)
{
    int i = blockIdx.x * blockDim.x + threadIdx.x;
    if (i >= n4) return;
    float4 v = ((const float4*)in)[i];
    uint32_t h0, l0, h1, l1;
    split2(v.x, v.y, h0, l0);
    split2(v.z, v.w, h1, l1);
    ((uint32_t*)hi)[i * 2 + 0] = h0;
    ((uint32_t*)hi)[i * 2 + 1] = h1;
    ((uint32_t*)lo)[i * 2 + 0] = l0;
    ((uint32_t*)lo)[i * 2 + 1] = l1;
}

// ---------------------------------------------------------------------------
// bf16x3 GEMM via mma.sync (unchanged from round 3 — proven)
// ---------------------------------------------------------------------------
#define GBM 128
#define GBN 128
#define GBK 64
#define TILE_B (GBM * GBK * 2)
#define STAGE_B (4 * TILE_B)
#define GEMM_SMEM (2 * STAGE_B)

__device__ __forceinline__ void cp_tile(
    uint32_t sbase, const __nv_bfloat16* __restrict__ g,
    int r0, int k0, int ldk, int tid)
{
#pragma unroll
    for (int it = 0; it < 4; it++) {
        int idx = tid + it * 256;
        int row = idx >> 3;
        int ch = idx & 7;
        uint32_t so = sbase + SWZ128((uint32_t)(row * 128 + ch * 16));
        const void* gp = (const void*)(g + (size_t)(r0 + row) * ldk + k0 + ch * 8);
        CP_ASYNC16(so, gp);
    }
}

__global__ __launch_bounds__(256, 1) void gemm_bf16x3(
    const __nv_bfloat16* __restrict__ Ah, const __nv_bfloat16* __restrict__ Al,
    const __nv_bfloat16* __restrict__ Bh, const __nv_bfloat16* __restrict__ Bl,
    const float* __restrict__ bias, float* __restrict__ C,
    int M, int N, int K)
{
    extern __shared__ char smem[];
    const uint32_t sb = smem_u32(smem);
    const int tid = threadIdx.x;
    const int wid = tid >> 5;
    const int lane = tid & 31;
    const int wm = wid >> 2;
    const int wn = wid & 3;
    const int m0 = blockIdx.y * GBM;
    const int n0 = blockIdx.x * GBN;

    float acc[4][4][4];
#pragma unroll
    for (int mf = 0; mf < 4; mf++)
#pragma unroll
        for (int nf = 0; nf < 4; nf++)
#pragma unroll
            for (int r = 0; r < 4; r++) acc[mf][nf][r] = 0.0f;

    const uint32_t arow = (uint32_t)(wm * 64 + (lane & 15));
    const uint32_t brow = (uint32_t)(wn * 32 + (lane & 15));
    const uint32_t khalf = (uint32_t)((lane >> 4) << 4);

    const int nk = K / GBK;

    {
        cp_tile(sb + 0 * TILE_B, Ah, m0, 0, K, tid);
        cp_tile(sb + 1 * TILE_B, Al, m0, 0, K, tid);
        cp_tile(sb + 2 * TILE_B, Bh, n0, 0, K, tid);
        cp_tile(sb + 3 * TILE_B, Bl, n0, 0, K, tid);
        CP_COMMIT();
    }

    for (int c = 0; c < nk; c++) {
        const uint32_t st = (uint32_t)(c & 1) * STAGE_B;
        if (c + 1 < nk) {
            const uint32_t st2 = (uint32_t)((c + 1) & 1) * STAGE_B;
            const int k0 = (c + 1) * GBK;
            cp_tile(sb + st2 + 0 * TILE_B, Ah, m0, k0, K, tid);
            cp_tile(sb + st2 + 1 * TILE_B, Al, m0, k0, K, tid);
            cp_tile(sb + st2 + 2 * TILE_B, Bh, n0, k0, K, tid);
            cp_tile(sb + st2 + 3 * TILE_B, Bl, n0, k0, K, tid);
            CP_COMMIT();
            CP_WAIT(1);
        } else {
            CP_WAIT(0);
        }
        __syncthreads();

        const uint32_t aH = sb + st + 0 * TILE_B;
        const uint32_t aL = sb + st + 1 * TILE_B;
        const uint32_t bH = sb + st + 2 * TILE_B;
        const uint32_t bL = sb + st + 3 * TILE_B;

#pragma unroll
        for (int ks = 0; ks < 4; ks++) {
            const uint32_t kb = (uint32_t)(ks * 32) + khalf;
            uint32_t ah[4][4], al[4][4], bh[2][4], bl[2][4];
#pragma unroll
            for (int mf = 0; mf < 4; mf++) {
                uint32_t off = SWZ128((arow + mf * 16) * 128 + kb);
                LDSM4(ah[mf], aH + off);
                LDSM4(al[mf], aL + off);
            }
#pragma unroll
            for (int nf2 = 0; nf2 < 2; nf2++) {
                uint32_t off = SWZ128((brow + nf2 * 16) * 128 + kb);
                LDSM4(bh[nf2], bH + off);
                LDSM4(bl[nf2], bL + off);
            }
#pragma unroll
            for (int mf = 0; mf < 4; mf++) {
#pragma unroll
                for (int nf2 = 0; nf2 < 2; nf2++) {
                    MMA16816(acc[mf][nf2 * 2 + 0], ah[mf], bh[nf2][0], bh[nf2][2]);
                    MMA16816(acc[mf][nf2 * 2 + 1], ah[mf], bh[nf2][1], bh[nf2][3]);
                    MMA16816(acc[mf][nf2 * 2 + 0], ah[mf], bl[nf2][0], bl[nf2][2]);
                    MMA16816(acc[mf][nf2 * 2 + 1], ah[mf], bl[nf2][1], bl[nf2][3]);
                    MMA16816(acc[mf][nf2 * 2 + 0], al[mf], bh[nf2][0], bh[nf2][2]);
                    MMA16816(acc[mf][nf2 * 2 + 1], al[mf], bh[nf2][1], bh[nf2][3]);
                }
            }
        }
        __syncthreads();
    }

#pragma unroll
    for (int mf = 0; mf < 4; mf++) {
        const int mrow = m0 + wm * 64 + mf * 16 + (lane >> 2);
#pragma unroll
        for (int nf = 0; nf < 4; nf++) {
            const int ncol = n0 + wn * 32 + nf * 8 + (lane & 3) * 2;
            const float b0 = bias[ncol];
            const float b1 = bias[ncol + 1];
            float2 v0, v1;
            v0.x = acc[mf][nf][0] + b0; v0.y = acc[mf][nf][1] + b1;
            v1.x = acc[mf][nf][2] + b0; v1.y = acc[mf][nf][3] + b1;
            *(float2*)(C + (size_t)mrow * N + ncol) = v0;
            *(float2*)(C + (size_t)(mrow + 8) * N + ncol) = v1;
        }
    }
}

// ---------------------------------------------------------------------------
// Tensor-core sliding-window attention (bf16x3 split, flash-style).
// Block = (64-query chunk, head), 128 threads (4 warps, 16 query rows each).
// 9 key tiles of 64 cover [q0-256, q0+318]; OOR keys loaded as zero and kept
// in-band (matches reference: padded zeros included in softmax denominator).
// Q pre-scaled by 0.125. SMEM: Qh,Ql,Kh,Kl (k-major, SW128), Vh,Vl
// ([key][dim] row-major, consumed via ldmatrix.trans). Writes bf16 hi/lo
// output splits directly (feeds GEMM2).
// ---------------------------------------------------------------------------
#define ATN_SMEM (6 * 8192)

__global__ __launch_bounds__(128) void attn_mma(
    const float* __restrict__ qkv,
    __nv_bfloat16* __restrict__ o_h, __nv_bfloat16* __restrict__ o_l)
{
    extern __shared__ char smc[];
    const uint32_t sb = smem_u32(smc);
    const uint32_t sQh = sb, sQl = sb + 8192;
    const uint32_t sKh = sb + 16384, sKl = sb + 24576;
    const uint32_t sVh = sb + 32768, sVl = sb + 40960;
    char* cQh = smc;        char* cQl = smc + 8192;
    char* cKh = smc + 16384; char* cKl = smc + 24576;
    char* cVh = smc + 32768; char* cVl = smc + 40960;

    const int h = blockIdx.y;
    const int q0 = blockIdx.x * 64;
    const int tid = threadIdx.x;
    const int w = tid >> 5;
    const int lane = tid & 31;

    // ---- load Q once (pre-scaled by 0.125), split hi/lo, swizzled ----
    for (int idx = tid; idx < 1024; idx += 128) {
        const int row = idx >> 4;
        const int seg = (idx & 15) * 4;              // dim
        float4 v = *(const float4*)(qkv + (size_t)(q0 + row) * 3072 + h * 64 + seg);
        v.x *= 0.125f; v.y *= 0.125f; v.z *= 0.125f; v.w *= 0.125f;
        uint32_t h0, l0, h1, l1;
        split2(v.x, v.y, h0, l0);
        split2(v.z, v.w, h1, l1);
        const uint32_t so = SWZ128((uint32_t)(row * 128 + seg * 2));
        *(uint2*)(cQh + so) = make_uint2(h0, h1);
        *(uint2*)(cQl + so) = make_uint2(l0, l1);
    }

    float m_run[2] = {-INFINITY, -INFINITY};
    float l_run[2] = {0.0f, 0.0f};
    float oacc[8][4];
#pragma unroll
    for (int nf = 0; nf < 8; nf++)
#pragma unroll
        for (int r = 0; r < 4; r++) oacc[nf][r] = 0.0f;

    const uint32_t lrow = (uint32_t)(lane & 15);
    const uint32_t khalf = (uint32_t)((lane >> 4) << 4);
    const int r0l = w * 16 + (lane >> 2);   // local query row (and +8)
    const int nc0 = (lane & 3) * 2;

    for (int t = 0; t < 9; t++) {
        const int j0 = q0 - 256 + t * 64;
        __syncthreads();   // previous tile's smem reads done

        // ---- load K/V tile (zero-fill OOR), split hi/lo ----
        for (int idx = tid; idx < 1024; idx += 128) {
            const int row = idx >> 4;
            const int seg = (idx & 15) * 4;
            const int j = j0 + row;
            float4 kv = make_float4(0.f, 0.f, 0.f, 0.f);
            float4 vv = make_float4(0.f, 0.f, 0.f, 0.f);
            if (j >= 0 && j < S_LEN) {
                const float* base = qkv + (size_t)j * 3072 + h * 64 + seg;
                kv = *(const float4*)(base + 1024);
                vv = *(const float4*)(base + 2048);
            }
            uint32_t h0, l0, h1, l1;
            const uint32_t so = SWZ128((uint32_t)(row * 128 + seg * 2));
            split2(kv.x, kv.y, h0, l0);
            split2(kv.z, kv.w, h1, l1);
            *(uint2*)(cKh + so) = make_uint2(h0, h1);
            *(uint2*)(cKl + so) = make_uint2(l0, l1);
            split2(vv.x, vv.y, h0, l0);
            split2(vv.z, vv.w, h1, l1);
            *(uint2*)(cVh + so) = make_uint2(h0, h1);
            *(uint2*)(cVl + so) = make_uint2(l0, l1);
        }
        __syncthreads();

        // ---- S = Q K^T (bf16x3) ----
        float sacc[8][4];
#pragma unroll
        for (int nf = 0; nf < 8; nf++)
#pragma unroll
            for (int r = 0; r < 4; r++) sacc[nf][r] = 0.0f;

#pragma unroll
        for (int ks = 0; ks < 4; ks++) {
            const uint32_t kb = (uint32_t)(ks * 32) + khalf;
            uint32_t qh_f[4], ql_f[4];
            {
                const uint32_t off = SWZ128((uint32_t)((w * 16 + lrow) * 128) + kb);
                LDSM4(qh_f, sQh + off);
                LDSM4(ql_f, sQl + off);
            }
#pragma unroll
            for (int g = 0; g < 4; g++) {
                const uint32_t off = SWZ128((uint32_t)((g * 16 + lrow) * 128) + kb);
                uint32_t kh_f[4], kl_f[4];
                LDSM4(kh_f, sKh + off);
                LDSM4(kl_f, sKl + off);
                MMA16816(sacc[2 * g + 0], qh_f, kh_f[0], kh_f[2]);
                MMA16816(sacc[2 * g + 1], qh_f, kh_f[1], kh_f[3]);
                MMA16816(sacc[2 * g + 0], qh_f, kl_f[0], kl_f[2]);
                MMA16816(sacc[2 * g + 1], qh_f, kl_f[1], kl_f[3]);
                MMA16816(sacc[2 * g + 0], ql_f, kh_f[0], kh_f[2]);
                MMA16816(sacc[2 * g + 1], ql_f, kh_f[1], kh_f[3]);
            }
        }

        // ---- band mask + online softmax ----
#pragma unroll
        for (int e = 0; e < 2; e++) {
            const int r = r0l + e * 8;
            float mx = -INFINITY;
#pragma unroll
            for (int nf = 0; nf < 8; nf++) {
#pragma unroll
                for (int c = 0; c < 2; c++) {
                    const int col = t * 64 + nf * 8 + nc0 + c;
                    const int rel = col - r;
                    float v = sacc[nf][e * 2 + c];
                    if (!(rel >= 0 && rel < WIN)) v = -INFINITY;
                    sacc[nf][e * 2 + c] = v;
                    mx = fmaxf(mx, v);
                }
            }
            mx = fmaxf(mx, __shfl_xor_sync(0xFFFFFFFFu, mx, 1));
            mx = fmaxf(mx, __shfl_xor_sync(0xFFFFFFFFu, mx, 2));

            const float m_new = fmaxf(m_run[e], mx);
            const float cc = __expf(m_run[e] - m_new);
            m_run[e] = m_new;

            float rs = 0.0f;
#pragma unroll
            for (int nf = 0; nf < 8; nf++) {
#pragma unroll
                for (int c = 0; c < 2; c++) {
                    const float p = __expf(sacc[nf][e * 2 + c] - m_new);
                    sacc[nf][e * 2 + c] = p;
                    rs += p;
                }
            }
            rs += __shfl_xor_sync(0xFFFFFFFFu, rs, 1);
            rs += __shfl_xor_sync(0xFFFFFFFFu, rs, 2);
            l_run[e] = l_run[e] * cc + rs;

#pragma unroll
            for (int nf = 0; nf < 8; nf++) {
                oacc[nf][e * 2 + 0] *= cc;
                oacc[nf][e * 2 + 1] *= cc;
            }
        }

        // ---- O += P V (bf16x3; P frags built from sacc, no shuffles) ----
#pragma unroll
        for (int j = 0; j < 4; j++) {       // key 16-groups
            uint32_t ph_f[4], pl_f[4];
            split2(sacc[2 * j][0], sacc[2 * j][1], ph_f[0], pl_f[0]);
            split2(sacc[2 * j][2], sacc[2 * j][3], ph_f[1], pl_f[1]);
            split2(sacc[2 * j + 1][0], sacc[2 * j + 1][1], ph_f[2], pl_f[2]);
            split2(sacc[2 * j + 1][2], sacc[2 * j + 1][3], ph_f[3], pl_f[3]);

            const uint32_t mi = (uint32_t)(lane >> 3);
            const uint32_t rsel = (uint32_t)(lane & 7);
            const uint32_t vrow = (uint32_t)(j * 16) + (mi & 1) * 8 + rsel;
            const uint32_t vcolb = (mi >> 1) * 16;
#pragma unroll
            for (int g = 0; g < 4; g++) {
                const uint32_t off = SWZ128(vrow * 128 + (uint32_t)(g * 32) + vcolb);
                uint32_t vh_f[4], vl_f[4];
                LDSM4T(vh_f, sVh + off);
                LDSM4T(vl_f, sVl + off);
                MMA16816(oacc[2 * g + 0], ph_f, vh_f[0], vh_f[1]);
                MMA16816(oacc[2 * g + 1], ph_f, vh_f[2], vh_f[3]);
                MMA16816(oacc[2 * g + 0], ph_f, vl_f[0], vl_f[1]);
                MMA16816(oacc[2 * g + 1], ph_f, vl_f[2], vl_f[3]);
                MMA16816(oacc[2 * g + 0], pl_f, vh_f[0], vh_f[1]);
                MMA16816(oacc[2 * g + 1], pl_f, vh_f[2], vh_f[3]);
            }
        }
    }

    // ---- epilogue: normalize and write bf16 hi/lo splits ----
#pragma unroll
    for (int e = 0; e < 2; e++) {
        const float inv_l = 1.0f / l_run[e];
        const int row = q0 + r0l + e * 8;
#pragma unroll
        for (int nf = 0; nf < 8; nf++) {
            const float v0 = oacc[nf][e * 2 + 0] * inv_l;
            const float v1 = oacc[nf][e * 2 + 1] * inv_l;
            uint32_t hp, lp;
            split2(v0, v1, hp, lp);
            const size_t gidx = (size_t)row * D_MODEL + h * 64 + nf * 8 + nc0;
            *(uint32_t*)((char*)o_h + gidx * 2) = hp;
            *(uint32_t*)((char*)o_l + gidx * 2) = lp;
        }
    }
}

// ---------------------------------------------------------------------------
extern "C" void kernel_launch(void* const* d_in, const int* in_sizes, int n_in,
                              void* d_out, int out_size)
{
    const float* x    = (const float*)d_in[0];
    const float* Wqkv = (const float*)d_in[1];
    const float* bqkv = (const float*)d_in[2];
    const float* Wout = (const float*)d_in[3];
    const float* bout = (const float*)d_in[4];
    float* out = (float*)d_out;
    (void)in_sizes; (void)n_in; (void)out_size;

    float* qkv_p;
    __nv_bfloat16 *xh, *xl, *wqh, *wql, *woh, *wol, *oh, *ol;
    cudaGetSymbolAddress((void**)&qkv_p, g_qkv);
    cudaGetSymbolAddress((void**)&xh, g_xh);
    cudaGetSymbolAddress((void**)&xl, g_xl);
    cudaGetSymbolAddress((void**)&wqh, g_wqh);
    cudaGetSymbolAddress((void**)&wql, g_wql);
    cudaGetSymbolAddress((void**)&woh, g_woh);
    cudaGetSymbolAddress((void**)&wol, g_wol);
    cudaGetSymbolAddress((void**)&oh, g_oh);
    cudaGetSymbolAddress((void**)&ol, g_ol);

    cudaFuncSetAttribute(gemm_bf16x3,
                         cudaFuncAttributeMaxDynamicSharedMemorySize, GEMM_SMEM);
    cudaFuncSetAttribute(attn_mma,
                         cudaFuncAttributeMaxDynamicSharedMemorySize, ATN_SMEM);

    // Splits
    {
        int n4 = (S_LEN * D_MODEL) / 4;
        split_bf16<<<(n4 + 255) / 256, 256>>>(x, xh, xl, n4);
    }
    {
        int n4 = (3 * D_MODEL * D_MODEL) / 4;
        split_bf16<<<(n4 + 255) / 256, 256>>>(Wqkv, wqh, wql, n4);
    }
    {
        int n4 = (D_MODEL * D_MODEL) / 4;
        split_bf16<<<(n4 + 255) / 256, 256>>>(Wout, woh, wol, n4);
    }

    // 1) QKV projection: [4096,3072]
    {
        dim3 grid(3 * D_MODEL / GBN, S_LEN / GBM);
        gemm_bf16x3<<<grid, 256, GEMM_SMEM>>>(xh, xl, wqh, wql, bqkv, qkv_p,
                                              S_LEN, 3 * D_MODEL, D_MODEL);
    }

    // 2) Sliding-window attention (tensor cores, writes bf16 splits)
    {
        dim3 grid(S_LEN / 64, H_HEADS);
        attn_mma<<<grid, 128, ATN_SMEM>>>(qkv_p, oh, ol);
    }

    // 3) Output projection: [4096,1024]
    {
        dim3 grid(D_MODEL / GBN, S_LEN / GBM);
        gemm_bf16x3<<<grid, 256, GEMM_SMEM>>>(oh, ol, woh, wol, bout, out,
                                              S_LEN, D_MODEL, D_MODEL);
    }
}